// round 3
// baseline (speedup 1.0000x reference)
#include <cuda_runtime.h>
#include <math.h>

// ---------------- problem constants ----------------
#define BB   2
#define TT   2048          // T after CLS prepend
#define SSQ  2048          // encoder seq len
#define DD   256
#define HH   8
#define DHH  32
#define FFD  2048
#define VV   25426
#define MROWS (BB*TT)      // 4096
#define NLOGITS (104144896LL)  // MROWS * VV

// ---------------- scratch (device globals; no allocs allowed) ----------------
__device__ float g_x   [MROWS*DD];
__device__ float g_q   [MROWS*DD];
__device__ float g_k   [MROWS*DD];
__device__ float g_v   [MROWS*DD];
__device__ float g_attn[MROWS*DD];
__device__ float g_proj[MROWS*DD];
__device__ float g_enc [BB*SSQ*DD];
__device__ float g_ff  [MROWS*FFD];
__device__ int   g_tgt [MROWS];

// ---------------- embedding + positional encoding ----------------
// x = emb[tgt] + (emb[tgt] + pe) = 2*emb + pe ; also materialize tgt ids (CLS=VOCAB at t=0)
__global__ void embed_kernel(const int* __restrict__ tgt_in, const float* __restrict__ emb,
                             float* __restrict__ x, int* __restrict__ tgtbuf) {
    int row = blockIdx.x;            // b*TT + t
    int d   = threadIdx.x;           // 0..255
    int b = row >> 11;
    int t = row & (TT-1);
    int id = (t == 0) ? VV : tgt_in[b*(TT-1) + (t-1)];
    if (d == 0) tgtbuf[row] = id;
    // pe: even d -> sin(pos*div), odd d -> cos(pos*div), div = exp(-(d&~1)*ln(1e4)/256)
    double div = exp(-(double)(d & ~1) * (9.210340371976184 / 256.0));
    float ang = (float)((double)t * div);
    float pe = (d & 1) ? cosf(ang) : sinf(ang);
    x[row*DD + d] = 2.0f * emb[(size_t)id*DD + d] + pe;
}

// enc = where(src!=0, enc_in, 0)
__global__ void encmask_kernel(const int* __restrict__ src, const float* __restrict__ enc_in,
                               float* __restrict__ enc) {
    int row = blockIdx.x;
    int d   = threadIdx.x;
    float v = (src[row] != 0) ? enc_in[(size_t)row*DD + d] : 0.0f;
    enc[(size_t)row*DD + d] = v;
}

// ---------------- SGEMM: C[M,N] = A[M,K] @ B[K,N] (+bias)(+gelu) ----------------
// 128x128 tile, BK=16, 256 threads, 8x8 per thread (split 4+4 for conflict-free LDS.128).
// MODE: 0=none, 1=+bias, 2=+bias+exact gelu
template<int MODE>
__global__ __launch_bounds__(256)
void sgemm_kernel(const float* __restrict__ A, const float* __restrict__ B,
                  const float* __restrict__ bias, float* __restrict__ C,
                  int M, int N, int K) {
    __shared__ float As[16][132];   // padded: 2-way max store conflict, 16B-aligned reads
    __shared__ float Bs[16][128];

    int tid = threadIdx.x;
    int tx = tid & 15;
    int ty = tid >> 4;
    int rowBase = blockIdx.y * 128;
    int colBase = blockIdx.x * 128;

    float acc[8][8];
    #pragma unroll
    for (int i = 0; i < 8; i++)
        #pragma unroll
        for (int j = 0; j < 8; j++) acc[i][j] = 0.0f;

    const float* Aptr = A + (size_t)rowBase * K;

    for (int k0 = 0; k0 < K; k0 += 16) {
        // A tile: 128 rows x 16 k, float4 loads, store transposed As[k][m]
        #pragma unroll
        for (int i = 0; i < 2; i++) {
            int idx = tid + i*256;           // float4 index 0..511
            int r  = idx >> 2;               // 0..127
            int kk = (idx & 3) << 2;         // 0,4,8,12
            float4 a4 = *(const float4*)(Aptr + (size_t)r*K + k0 + kk);
            As[kk+0][r] = a4.x; As[kk+1][r] = a4.y;
            As[kk+2][r] = a4.z; As[kk+3][r] = a4.w;
        }
        // B tile: 16 k rows x 128 cols, scalar w/ column guard (N may be 25426)
        #pragma unroll
        for (int i = 0; i < 8; i++) {
            int idx = tid + i*256;           // 0..2047
            int kk = idx >> 7;
            int c  = idx & 127;
            int gc = colBase + c;
            Bs[kk][c] = (gc < N) ? B[(size_t)(k0+kk)*N + gc] : 0.0f;
        }
        __syncthreads();

        #pragma unroll
        for (int kk = 0; kk < 16; kk++) {
            float a[8], b[8];
            #pragma unroll
            for (int i = 0; i < 4; i++) { a[i]   = As[kk][ty*4 + i];
                                          a[i+4] = As[kk][64 + ty*4 + i]; }
            #pragma unroll
            for (int j = 0; j < 4; j++) { b[j]   = Bs[kk][tx*4 + j];
                                          b[j+4] = Bs[kk][64 + tx*4 + j]; }
            #pragma unroll
            for (int i = 0; i < 8; i++)
                #pragma unroll
                for (int j = 0; j < 8; j++)
                    acc[i][j] += a[i] * b[j];
        }
        __syncthreads();
    }

    #pragma unroll
    for (int i = 0; i < 8; i++) {
        int r = rowBase + ((i < 4) ? (ty*4 + i) : (64 + ty*4 + (i-4)));
        #pragma unroll
        for (int j = 0; j < 8; j++) {
            int c = colBase + ((j < 4) ? (tx*4 + j) : (64 + tx*4 + (j-4)));
            if (c < N) {
                float v = acc[i][j];
                if (MODE >= 1) v += bias[c];
                if (MODE == 2) v = 0.5f * v * (1.0f + erff(v * 0.70710678118654752f));
                C[(size_t)r*N + c] = v;
            }
        }
    }
}

// ---------------- attention (flash-style, fp32, online softmax) ----------------
// Layout: Q/K/V are [rows, 256] with head h at cols h*32..h*32+31.
// Block: 256 threads = 64 query rows x 4 key slices. Each thread owns one
// (query row, key-slice) with private (m,l,o[32]); slices merged via smem.
// causal!=0: key j valid iff j<=i AND tgt[b*Tk+j]!=0. causal==0: all keys valid.
#define AT_ROWS 64
#define AT_SL   4
#define AT_CK   32

__global__ __launch_bounds__(256)
void attn_kernel(const float* __restrict__ Qm, const float* __restrict__ Km,
                 const float* __restrict__ Vm, float* __restrict__ Om,
                 const int* __restrict__ tgt, int Tq, int Tk, int causal) {
    // flat smem, phase-overlaid:
    //  phase A: K/V chunks: KS/VS at [(s*32+j)*64 + d(+32)]  (8192 floats)
    //  phase B: per-slice o:  OB at [(s*64+r)*33 + d]        (8448 floats)
    __shared__ float kvbuf[4*64*33];
    __shared__ int   pvalid[AT_SL][AT_CK];
    __shared__ float sm_m[AT_SL][AT_ROWS];
    __shared__ float sm_l[AT_SL][AT_ROWS];

    int bh = blockIdx.x;
    int b = bh >> 3;
    int h = bh & 7;
    int tid = threadIdx.x;
    int slice = tid >> 6;            // 0..3
    int rloc  = tid & 63;            // 0..63
    int qrow  = blockIdx.y * AT_ROWS + rloc;

    float q[32], o[32];
    const float* qp = Qm + ((size_t)(b*Tq + qrow))*DD + h*DHH;
    #pragma unroll
    for (int d = 0; d < 32; d++) { q[d] = qp[d]; o[d] = 0.0f; }
    float m = -3.4e38f, l = 0.0f;
    const float scale = 0.17677669529663687f;   // 1/sqrt(32)

    int kbeg   = slice * (Tk / AT_SL);
    int chunks = (Tk / AT_SL) / AT_CK;          // 16

    for (int c = 0; c < chunks; c++) {
        int j0 = kbeg + c * AT_CK;
        // cooperative load of this slice's K/V chunk (32 keys x 32 dims, float4)
        #pragma unroll
        for (int i = 0; i < 4; i++) {
            int fi = rloc + i*64;               // float4 index 0..255
            int r  = fi >> 3;
            int dd = (fi & 7) << 2;
            size_t gro = ((size_t)(b*Tk + j0 + r))*DD + h*DHH + dd;
            *(float4*)&kvbuf[((slice*32 + r) << 6) + dd]      = *(const float4*)(Km + gro);
            *(float4*)&kvbuf[((slice*32 + r) << 6) + 32 + dd] = *(const float4*)(Vm + gro);
        }
        if (rloc < AT_CK) {
            int jg = j0 + rloc;
            pvalid[slice][rloc] = causal ? (tgt[b*Tk + jg] != 0) : 1;
        }
        __syncthreads();

        #pragma unroll 1
        for (int j = 0; j < AT_CK; j++) {
            int jg = j0 + j;
            bool valid = pvalid[slice][j] && (!causal || jg <= qrow);
            if (valid) {
                const float* kr = &kvbuf[((slice*32 + j) << 6)];
                float s = 0.0f;
                #pragma unroll
                for (int d = 0; d < 32; d++) s += q[d] * kr[d];
                s *= scale;
                const float* vr = kr + 32;
                if (s > m) {
                    float corr = expf(m - s);   // exp(-inf)=0 handles first key
                    l = l * corr + 1.0f;
                    #pragma unroll
                    for (int d = 0; d < 32; d++) o[d] = o[d]*corr + vr[d];
                    m = s;
                } else {
                    float p = expf(s - m);
                    l += p;
                    #pragma unroll
                    for (int d = 0; d < 32; d++) o[d] += p * vr[d];
                }
            }
        }
        __syncthreads();
    }

    // merge 4 slices per query row
    sm_m[slice][rloc] = m;
    sm_l[slice][rloc] = l;
    #pragma unroll
    for (int d = 0; d < 32; d++) kvbuf[(slice*64 + rloc)*33 + d] = o[d];
    __syncthreads();

    if (slice == 0) {
        float M2 = sm_m[0][rloc];
        #pragma unroll
        for (int s = 1; s < 4; s++) M2 = fmaxf(M2, sm_m[s][rloc]);
        float L = 0.0f;
        float oo[32];
        #pragma unroll
        for (int d = 0; d < 32; d++) oo[d] = 0.0f;
        #pragma unroll
        for (int s = 0; s < 4; s++) {
            float w = expf(sm_m[s][rloc] - M2);
            L += sm_l[s][rloc] * w;
            const float* ob = &kvbuf[(s*64 + rloc)*33];
            #pragma unroll
            for (int d = 0; d < 32; d++) oo[d] += ob[d] * w;
        }
        float inv = 1.0f / L;
        float* op = Om + ((size_t)(b*Tq + qrow))*DD + h*DHH;
        #pragma unroll
        for (int d = 0; d < 32; d++) op[d] = oo[d] * inv;
    }
}

// ---------------- residual add + LayerNorm (row = 256 elems = 256 threads) ----------------
__global__ void add_ln_kernel(const float* __restrict__ X, const float* __restrict__ Y,
                              const float* __restrict__ g, const float* __restrict__ be,
                              float* __restrict__ out) {
    int row = blockIdx.x;
    int d   = threadIdx.x;
    float v = X[(size_t)row*DD + d] + Y[(size_t)row*DD + d];

    __shared__ float red1[8], red2[8];
    float s = v;
    #pragma unroll
    for (int off = 16; off; off >>= 1) s += __shfl_xor_sync(0xffffffffu, s, off);
    if ((d & 31) == 0) red1[d >> 5] = s;
    __syncthreads();
    float tot = red1[0]+red1[1]+red1[2]+red1[3]+red1[4]+red1[5]+red1[6]+red1[7];
    float mean = tot * (1.0f/256.0f);
    float c = v - mean;
    float s2 = c * c;
    #pragma unroll
    for (int off = 16; off; off >>= 1) s2 += __shfl_xor_sync(0xffffffffu, s2, off);
    if ((d & 31) == 0) red2[d >> 5] = s2;
    __syncthreads();
    float tot2 = red2[0]+red2[1]+red2[2]+red2[3]+red2[4]+red2[5]+red2[6]+red2[7];
    float var = tot2 * (1.0f/256.0f);
    float rstd = 1.0f / sqrtf(var + 1e-5f);
    out[(size_t)row*DD + d] = c * rstd * g[d] + be[d];
}

// ---------------- second output: tgt ids with position 0 zeroed ----------------
__global__ void write_ids_kernel(const int* __restrict__ tgt, float* __restrict__ out) {
    int i = blockIdx.x * 256 + threadIdx.x;
    if (i < MROWS) {
        int t = i & (TT-1);
        out[NLOGITS + i] = (t == 0) ? 0.0f : (float)tgt[i];
    }
}

// ---------------- host orchestration ----------------
extern "C" void kernel_launch(void* const* d_in, const int* in_sizes, int n_in,
                              void* d_out, int out_size) {
    const int*   src    = (const int*)  d_in[0];
    const int*   tgt_in = (const int*)  d_in[1];
    const float* enc_in = (const float*)d_in[2];
    const float* emb    = (const float*)d_in[3];
    const float* Wq_s   = (const float*)d_in[4];
    const float* Wk_s   = (const float*)d_in[5];
    const float* Wv_s   = (const float*)d_in[6];
    const float* Wo_s   = (const float*)d_in[7];
    const float* bo_s   = (const float*)d_in[8];
    const float* Wq_c   = (const float*)d_in[9];
    const float* Wk_c   = (const float*)d_in[10];
    const float* Wv_c   = (const float*)d_in[11];
    const float* Wo_c   = (const float*)d_in[12];
    const float* bo_c   = (const float*)d_in[13];
    const float* W1     = (const float*)d_in[14];
    const float* b1     = (const float*)d_in[15];
    const float* W2     = (const float*)d_in[16];
    const float* b2     = (const float*)d_in[17];
    const float* g1     = (const float*)d_in[18];
    const float* be1    = (const float*)d_in[19];
    const float* g2     = (const float*)d_in[20];
    const float* be2    = (const float*)d_in[21];
    const float* g3     = (const float*)d_in[22];
    const float* be3    = (const float*)d_in[23];
    const float* Wf     = (const float*)d_in[24];
    const float* bf     = (const float*)d_in[25];

    float *px, *pq, *pk, *pv, *pattn, *pproj, *penc, *pff;
    int *ptgt;
    cudaGetSymbolAddress((void**)&px,    g_x);
    cudaGetSymbolAddress((void**)&pq,    g_q);
    cudaGetSymbolAddress((void**)&pk,    g_k);
    cudaGetSymbolAddress((void**)&pv,    g_v);
    cudaGetSymbolAddress((void**)&pattn, g_attn);
    cudaGetSymbolAddress((void**)&pproj, g_proj);
    cudaGetSymbolAddress((void**)&penc,  g_enc);
    cudaGetSymbolAddress((void**)&pff,   g_ff);
    cudaGetSymbolAddress((void**)&ptgt,  g_tgt);

    float* out = (float*)d_out;

    dim3 gDxD((DD + 127)/128, MROWS/128);     // (2, 32)
    dim3 gFF ((FFD + 127)/128, MROWS/128);    // (16, 32)
    dim3 gV  ((VV + 127)/128, MROWS/128);     // (199, 32)
    dim3 gAttn(BB*HH, TT/AT_ROWS);            // (16, 32)

    // embedding + encoder masking
    embed_kernel  <<<MROWS, 256>>>(tgt_in, emb, px, ptgt);
    encmask_kernel<<<BB*SSQ, 256>>>(src, enc_in, penc);

    // ---- self attention block ----
    sgemm_kernel<0><<<gDxD, 256>>>(px, Wq_s, nullptr, pq, MROWS, DD, DD);
    sgemm_kernel<0><<<gDxD, 256>>>(px, Wk_s, nullptr, pk, MROWS, DD, DD);
    sgemm_kernel<0><<<gDxD, 256>>>(px, Wv_s, nullptr, pv, MROWS, DD, DD);
    attn_kernel<<<gAttn, 256>>>(pq, pk, pv, pattn, ptgt, TT, TT, 1);
    sgemm_kernel<1><<<gDxD, 256>>>(pattn, Wo_s, bo_s, pproj, MROWS, DD, DD);
    add_ln_kernel<<<MROWS, 256>>>(px, pproj, g1, be1, px);

    // ---- cross attention block (no mask; enc rows already zeroed at pads) ----
    sgemm_kernel<0><<<gDxD, 256>>>(px,   Wq_c, nullptr, pq, MROWS, DD, DD);
    sgemm_kernel<0><<<gDxD, 256>>>(penc, Wk_c, nullptr, pk, BB*SSQ, DD, DD);
    sgemm_kernel<0><<<gDxD, 256>>>(penc, Wv_c, nullptr, pv, BB*SSQ, DD, DD);
    attn_kernel<<<gAttn, 256>>>(pq, pk, pv, pattn, ptgt, TT, SSQ, 0);
    sgemm_kernel<1><<<gDxD, 256>>>(pattn, Wo_c, bo_c, pproj, MROWS, DD, DD);
    add_ln_kernel<<<MROWS, 256>>>(px, pproj, g2, be2, px);

    // ---- feed-forward ----
    sgemm_kernel<2><<<gFF,  256>>>(px, W1, b1, pff,   MROWS, FFD, DD);   // +bias +gelu(exact)
    sgemm_kernel<1><<<gDxD, 256>>>(pff, W2, b2, pproj, MROWS, DD, FFD);
    add_ln_kernel<<<MROWS, 256>>>(px, pproj, g3, be3, px);

    // ---- vocab projection straight into d_out ----
    sgemm_kernel<1><<<gV, 256>>>(px, Wf, bf, out, MROWS, VV, DD);

    // ---- second output (tgt ids) if the harness buffer includes it ----
    if ((long long)out_size >= NLOGITS + MROWS) {
        write_ids_kernel<<<(MROWS + 255)/256, 256>>>(ptgt, out);
    }
}

// round 6
// speedup vs baseline: 1.5508x; 1.5508x over previous
#include <cuda_runtime.h>
#include <cuda_bf16.h>
#include <math.h>

// ---------------- problem constants ----------------
#define BB   2
#define TT   2048          // T after CLS prepend
#define SSQ  2048          // encoder seq len
#define DD   256
#define HH   8
#define DHH  32
#define FFD  2048
#define VV   25426
#define VVPAD 25472        // 199*128
#define MROWS (BB*TT)      // 4096
#define NLOGITS (104144896LL)  // MROWS * VV

// weight hi/lo buffer offsets (halves), layout [Npad][K]
#define OW_QS 0
#define OW_KS 65536
#define OW_VS 131072
#define OW_OS 196608
#define OW_QC 262144
#define OW_KC 327680
#define OW_VC 393216
#define OW_OC 458752
#define OW_W1 524288            // Npad=2048, K=256
#define OW_W2 1048576           // Npad=256,  K=2048
#define OW_WF 1572864           // Npad=25472, K=256
#define WTOT  8093696

// ---------------- scratch (device globals; no allocs allowed) ----------------
__device__ float g_x   [MROWS*DD];
__device__ float g_q   [MROWS*DD];
__device__ float g_k   [MROWS*DD];
__device__ float g_v   [MROWS*DD];
__device__ float g_attn[MROWS*DD];
__device__ float g_proj[MROWS*DD];
__device__ float g_enc [BB*SSQ*DD];
__device__ float g_ff  [MROWS*FFD];
__device__ int   g_tgt [MROWS];
__device__ __align__(16) __nv_bfloat16 g_whi[WTOT];
__device__ __align__(16) __nv_bfloat16 g_wlo[WTOT];

// ---------------- helpers ----------------
__device__ __forceinline__ unsigned packbf(float x, float y) {
    __nv_bfloat162 t;
    t.x = __float2bfloat16(x);
    t.y = __float2bfloat16(y);
    return *reinterpret_cast<unsigned*>(&t);
}
__device__ __forceinline__ void splitf(float v, float& hi, float& lo) {
    __nv_bfloat16 h = __float2bfloat16(v);
    hi = __bfloat162float(h);
    lo = v - hi;
}
// permuted k-pair column: within each group of 8 pairs, puts pair p and p+4 adjacent
__device__ __forceinline__ int colperm(int p) {
    return ((p >> 3) << 3) + ((p & 3) << 1) + ((p >> 2) & 1);
}

#define MMA_B16(c, a, b0_, b1_) \
  asm volatile("mma.sync.aligned.m16n8k16.row.col.f32.bf16.bf16.f32 " \
    "{%0,%1,%2,%3}, {%4,%5,%6,%7}, {%8,%9}, {%0,%1,%2,%3};" \
    : "+f"((c)[0]), "+f"((c)[1]), "+f"((c)[2]), "+f"((c)[3]) \
    : "r"((a)[0]), "r"((a)[1]), "r"((a)[2]), "r"((a)[3]), "r"(b0_), "r"(b1_))

// ---------------- weight transpose + hi/lo split ----------------
// W [K][N] fp32 row-major  ->  hi/lo [Npad][K] bf16 row-major (zero pad rows)
// grid (Npad/32, K/32), block (32, 8)
__global__ void wsplit_kernel(const float* __restrict__ W,
                              __nv_bfloat16* __restrict__ hi,
                              __nv_bfloat16* __restrict__ lo,
                              int K, int N) {
    __shared__ float t[32][33];
    int n0 = blockIdx.x * 32, k0 = blockIdx.y * 32;
    int tx = threadIdx.x, ty = threadIdx.y;
    #pragma unroll
    for (int i = 0; i < 4; i++) {
        int k = k0 + ty + i * 8;
        int n = n0 + tx;
        t[ty + i * 8][tx] = (n < N) ? W[(size_t)k * N + n] : 0.0f;
    }
    __syncthreads();
    #pragma unroll
    for (int i = 0; i < 4; i++) {
        int n = n0 + ty + i * 8;       // output row
        int k = k0 + tx;               // output col
        float v = t[tx][ty + i * 8];
        float h, l; splitf(v, h, l);
        hi[(size_t)n * K + k] = __float2bfloat16(h);
        lo[(size_t)n * K + k] = __float2bfloat16(l);
    }
}

// ---------------- bf16x3 tensor-core GEMM ----------------
// C[M,N] = A[M,K](fp32) @ Bt[N,K](bf16 hi/lo, pre-transposed)   (+bias)(+gelu)
// CTA tile 128x128, BK=32, 256 threads, warp tile 64x32 (2x4 warps), mma m16n8k16.
// MODE: 0=none, 1=+bias, 2=+bias+exact gelu
template<int MODE>
__global__ __launch_bounds__(256, 1)
void bf16gemm_kernel(const float* __restrict__ A,
                     const __nv_bfloat16* __restrict__ Bhi,
                     const __nv_bfloat16* __restrict__ Blo,
                     const float* __restrict__ bias,
                     float* __restrict__ C,
                     int M, int N, int K) {
    __shared__ __align__(16) unsigned As_hi[128 * 16];
    __shared__ __align__(16) unsigned As_lo[128 * 16];
    __shared__ __align__(16) unsigned Bs_hi[128 * 16];
    __shared__ __align__(16) unsigned Bs_lo[128 * 16];

    const int tid = threadIdx.x;
    const int lane = tid & 31, warp = tid >> 5;
    const int wr = (warp & 1) * 64, wc = (warp >> 1) * 32;
    const int g = lane >> 2, tg = lane & 3;
    const int rowBase = blockIdx.y * 128;
    const int colBase = blockIdx.x * 128;

    const float* Ab = A + (size_t)rowBase * K;

    float c[4][4][4];
    #pragma unroll
    for (int mf = 0; mf < 4; mf++)
        #pragma unroll
        for (int nf = 0; nf < 4; nf++)
            #pragma unroll
            for (int i = 0; i < 4; i++) c[mf][nf][i] = 0.0f;

    float4 aP[4];
    uint4  bhP[2], blP[2];

    auto loadG = [&](int k0) {
        #pragma unroll
        for (int i = 0; i < 4; i++) {
            int idx = tid + i * 256;
            int r = idx >> 3, kk = (idx & 7) << 2;
            aP[i] = *(const float4*)(Ab + (size_t)r * K + k0 + kk);
        }
        #pragma unroll
        for (int i = 0; i < 2; i++) {
            int idx = tid + i * 256;
            int n = idx >> 2, kk = (idx & 3) << 3;
            size_t o = (size_t)(colBase + n) * K + k0 + kk;
            bhP[i] = *(const uint4*)(Bhi + o);
            blP[i] = *(const uint4*)(Blo + o);
        }
    };
    auto storeS = [&]() {
        #pragma unroll
        for (int i = 0; i < 4; i++) {
            int idx = tid + i * 256;
            int r = idx >> 3, kk = (idx & 7) << 2;
            float h0, l0, h1, l1, h2, l2, h3, l3;
            splitf(aP[i].x, h0, l0); splitf(aP[i].y, h1, l1);
            splitf(aP[i].z, h2, l2); splitf(aP[i].w, h3, l3);
            int p0 = kk >> 1;
            int c0 = colperm(p0), c1 = colperm(p0 + 1);
            As_hi[r * 16 + c0] = packbf(h0, h1);
            As_hi[r * 16 + c1] = packbf(h2, h3);
            As_lo[r * 16 + c0] = packbf(l0, l1);
            As_lo[r * 16 + c1] = packbf(l2, l3);
        }
        #pragma unroll
        for (int i = 0; i < 2; i++) {
            int idx = tid + i * 256;
            int n = idx >> 2, kk = (idx & 3) << 3;
            int p0 = kk >> 1;
            const unsigned* vh = (const unsigned*)&bhP[i];
            const unsigned* vl = (const unsigned*)&blP[i];
            #pragma unroll
            for (int j = 0; j < 4; j++) {
                int cc = colperm(p0 + j);
                Bs_hi[n * 16 + cc] = vh[j];
                Bs_lo[n * 16 + cc] = vl[j];
            }
        }
    };

    loadG(0);
    for (int k0 = 0; k0 < K; k0 += 32) {
        storeS();
        __syncthreads();
        if (k0 + 32 < K) loadG(k0 + 32);

        #pragma unroll
        for (int s = 0; s < 2; s++) {
            unsigned ah[4][4], al[4][4];
            #pragma unroll
            for (int mf = 0; mf < 4; mf++) {
                int r0 = wr + mf * 16 + g;
                int o = s * 8 + tg * 2;
                uint2 t0 = *(const uint2*)&As_hi[r0 * 16 + o];
                uint2 t1 = *(const uint2*)&As_hi[(r0 + 8) * 16 + o];
                ah[mf][0] = t0.x; ah[mf][1] = t1.x; ah[mf][2] = t0.y; ah[mf][3] = t1.y;
                uint2 u0 = *(const uint2*)&As_lo[r0 * 16 + o];
                uint2 u1 = *(const uint2*)&As_lo[(r0 + 8) * 16 + o];
                al[mf][0] = u0.x; al[mf][1] = u1.x; al[mf][2] = u0.y; al[mf][3] = u1.y;
            }
            #pragma unroll
            for (int nf = 0; nf < 4; nf++) {
                int n0 = wc + nf * 8 + g;
                int o = s * 8 + tg * 2;
                uint2 bh = *(const uint2*)&Bs_hi[n0 * 16 + o];
                uint2 bl = *(const uint2*)&Bs_lo[n0 * 16 + o];
                #pragma unroll
                for (int mf = 0; mf < 4; mf++) {
                    MMA_B16(c[mf][nf], ah[mf], bh.x, bh.y);
                    MMA_B16(c[mf][nf], ah[mf], bl.x, bl.y);
                    MMA_B16(c[mf][nf], al[mf], bh.x, bh.y);
                }
            }
        }
        __syncthreads();
    }

    // epilogue
    #pragma unroll
    for (int mf = 0; mf < 4; mf++) {
        int r0 = rowBase + wr + mf * 16 + g;
        #pragma unroll
        for (int nf = 0; nf < 4; nf++) {
            int cc = colBase + wc + nf * 8 + tg * 2;
            #pragma unroll
            for (int i = 0; i < 4; i++) {
                int r = r0 + (i >> 1) * 8;
                int col = cc + (i & 1);
                if (col < N) {
                    float v = c[mf][nf][i];
                    if (MODE >= 1) v += bias[col];
                    if (MODE == 2) v = 0.5f * v * (1.0f + erff(v * 0.70710678118654752f));
                    C[(size_t)r * N + col] = v;
                }
            }
        }
    }
}

// ---------------- embedding + positional encoding ----------------
__global__ void embed_kernel(const int* __restrict__ tgt_in, const float* __restrict__ emb,
                             float* __restrict__ x, int* __restrict__ tgtbuf) {
    int row = blockIdx.x;            // b*TT + t
    int d   = threadIdx.x;           // 0..255
    int b = row >> 11;
    int t = row & (TT-1);
    int id = (t == 0) ? VV : tgt_in[b*(TT-1) + (t-1)];
    if (d == 0) tgtbuf[row] = id;
    double div = exp(-(double)(d & ~1) * (9.210340371976184 / 256.0));
    float ang = (float)((double)t * div);
    float pe = (d & 1) ? cosf(ang) : sinf(ang);
    x[row*DD + d] = 2.0f * emb[(size_t)id*DD + d] + pe;
}

__global__ void encmask_kernel(const int* __restrict__ src, const float* __restrict__ enc_in,
                               float* __restrict__ enc) {
    int row = blockIdx.x;
    int d   = threadIdx.x;
    float v = (src[row] != 0) ? enc_in[(size_t)row*DD + d] : 0.0f;
    enc[(size_t)row*DD + d] = v;
}

// ---------------- attention (flash-style, fp32, online softmax) ----------------
#define AT_ROWS 64
#define AT_SL   4
#define AT_CK   32

__global__ __launch_bounds__(256)
void attn_kernel(const float* __restrict__ Qm, const float* __restrict__ Km,
                 const float* __restrict__ Vm, float* __restrict__ Om,
                 const int* __restrict__ tgt, int Tq, int Tk, int causal) {
    __shared__ float kvbuf[4*64*33];
    __shared__ int   pvalid[AT_SL][AT_CK];
    __shared__ float sm_m[AT_SL][AT_ROWS];
    __shared__ float sm_l[AT_SL][AT_ROWS];

    int bh = blockIdx.x;
    int b = bh >> 3;
    int h = bh & 7;
    int tid = threadIdx.x;
    int slice = tid >> 6;
    int rloc  = tid & 63;
    int qrow  = blockIdx.y * AT_ROWS + rloc;

    float q[32], o[32];
    const float* qp = Qm + ((size_t)(b*Tq + qrow))*DD + h*DHH;
    #pragma unroll
    for (int d = 0; d < 32; d++) { q[d] = qp[d]; o[d] = 0.0f; }
    float m = -3.4e38f, l = 0.0f;
    const float scale = 0.17677669529663687f;

    int kbeg   = slice * (Tk / AT_SL);
    int chunks = (Tk / AT_SL) / AT_CK;

    for (int c = 0; c < chunks; c++) {
        int j0 = kbeg + c * AT_CK;
        #pragma unroll
        for (int i = 0; i < 4; i++) {
            int fi = rloc + i*64;
            int r  = fi >> 3;
            int dd = (fi & 7) << 2;
            size_t gro = ((size_t)(b*Tk + j0 + r))*DD + h*DHH + dd;
            *(float4*)&kvbuf[((slice*32 + r) << 6) + dd]      = *(const float4*)(Km + gro);
            *(float4*)&kvbuf[((slice*32 + r) << 6) + 32 + dd] = *(const float4*)(Vm + gro);
        }
        if (rloc < AT_CK) {
            int jg = j0 + rloc;
            pvalid[slice][rloc] = causal ? (tgt[b*Tk + jg] != 0) : 1;
        }
        __syncthreads();

        #pragma unroll 1
        for (int j = 0; j < AT_CK; j++) {
            int jg = j0 + j;
            bool valid = pvalid[slice][j] && (!causal || jg <= qrow);
            if (valid) {
                const float* kr = &kvbuf[((slice*32 + j) << 6)];
                float s = 0.0f;
                #pragma unroll
                for (int d = 0; d < 32; d++) s += q[d] * kr[d];
                s *= scale;
                const float* vr = kr + 32;
                if (s > m) {
                    float corr = expf(m - s);
                    l = l * corr + 1.0f;
                    #pragma unroll
                    for (int d = 0; d < 32; d++) o[d] = o[d]*corr + vr[d];
                    m = s;
                } else {
                    float p = expf(s - m);
                    l += p;
                    #pragma unroll
                    for (int d = 0; d < 32; d++) o[d] += p * vr[d];
                }
            }
        }
        __syncthreads();
    }

    sm_m[slice][rloc] = m;
    sm_l[slice][rloc] = l;
    #pragma unroll
    for (int d = 0; d < 32; d++) kvbuf[(slice*64 + rloc)*33 + d] = o[d];
    __syncthreads();

    if (slice == 0) {
        float M2 = sm_m[0][rloc];
        #pragma unroll
        for (int s = 1; s < 4; s++) M2 = fmaxf(M2, sm_m[s][rloc]);
        float L = 0.0f;
        float oo[32];
        #pragma unroll
        for (int d = 0; d < 32; d++) oo[d] = 0.0f;
        #pragma unroll
        for (int s = 0; s < 4; s++) {
            float w = expf(sm_m[s][rloc] - M2);
            L += sm_l[s][rloc] * w;
            const float* ob = &kvbuf[(s*64 + rloc)*33];
            #pragma unroll
            for (int d = 0; d < 32; d++) oo[d] += ob[d] * w;
        }
        float inv = 1.0f / L;
        float* op = Om + ((size_t)(b*Tq + qrow))*DD + h*DHH;
        #pragma unroll
        for (int d = 0; d < 32; d++) op[d] = oo[d] * inv;
    }
}

// ---------------- residual add + LayerNorm ----------------
__global__ void add_ln_kernel(const float* __restrict__ X, const float* __restrict__ Y,
                              const float* __restrict__ g, const float* __restrict__ be,
                              float* __restrict__ out) {
    int row = blockIdx.x;
    int d   = threadIdx.x;
    float v = X[(size_t)row*DD + d] + Y[(size_t)row*DD + d];

    __shared__ float red1[8], red2[8];
    float s = v;
    #pragma unroll
    for (int off = 16; off; off >>= 1) s += __shfl_xor_sync(0xffffffffu, s, off);
    if ((d & 31) == 0) red1[d >> 5] = s;
    __syncthreads();
    float tot = red1[0]+red1[1]+red1[2]+red1[3]+red1[4]+red1[5]+red1[6]+red1[7];
    float mean = tot * (1.0f/256.0f);
    float c = v - mean;
    float s2 = c * c;
    #pragma unroll
    for (int off = 16; off; off >>= 1) s2 += __shfl_xor_sync(0xffffffffu, s2, off);
    if ((d & 31) == 0) red2[d >> 5] = s2;
    __syncthreads();
    float tot2 = red2[0]+red2[1]+red2[2]+red2[3]+red2[4]+red2[5]+red2[6]+red2[7];
    float var = tot2 * (1.0f/256.0f);
    float rstd = 1.0f / sqrtf(var + 1e-5f);
    out[(size_t)row*DD + d] = c * rstd * g[d] + be[d];
}

// ---------------- second output: tgt ids with position 0 zeroed ----------------
__global__ void write_ids_kernel(const int* __restrict__ tgt, float* __restrict__ out) {
    int i = blockIdx.x * 256 + threadIdx.x;
    if (i < MROWS) {
        int t = i & (TT-1);
        out[NLOGITS + i] = (t == 0) ? 0.0f : (float)tgt[i];
    }
}

// ---------------- host orchestration ----------------
extern "C" void kernel_launch(void* const* d_in, const int* in_sizes, int n_in,
                              void* d_out, int out_size) {
    const int*   src    = (const int*)  d_in[0];
    const int*   tgt_in = (const int*)  d_in[1];
    const float* enc_in = (const float*)d_in[2];
    const float* emb    = (const float*)d_in[3];
    const float* Wq_s   = (const float*)d_in[4];
    const float* Wk_s   = (const float*)d_in[5];
    const float* Wv_s   = (const float*)d_in[6];
    const float* Wo_s   = (const float*)d_in[7];
    const float* bo_s   = (const float*)d_in[8];
    const float* Wq_c   = (const float*)d_in[9];
    const float* Wk_c   = (const float*)d_in[10];
    const float* Wv_c   = (const float*)d_in[11];
    const float* Wo_c   = (const float*)d_in[12];
    const float* bo_c   = (const float*)d_in[13];
    const float* W1     = (const float*)d_in[14];
    const float* b1     = (const float*)d_in[15];
    const float* W2     = (const float*)d_in[16];
    const float* b2     = (const float*)d_in[17];
    const float* g1     = (const float*)d_in[18];
    const float* be1    = (const float*)d_in[19];
    const float* g2     = (const float*)d_in[20];
    const float* be2    = (const float*)d_in[21];
    const float* g3     = (const float*)d_in[22];
    const float* be3    = (const float*)d_in[23];
    const float* Wf     = (const float*)d_in[24];
    const float* bf     = (const float*)d_in[25];

    float *px, *pq, *pk, *pv, *pattn, *pproj, *penc, *pff;
    int *ptgt;
    __nv_bfloat16 *whi, *wlo;
    cudaGetSymbolAddress((void**)&px,    g_x);
    cudaGetSymbolAddress((void**)&pq,    g_q);
    cudaGetSymbolAddress((void**)&pk,    g_k);
    cudaGetSymbolAddress((void**)&pv,    g_v);
    cudaGetSymbolAddress((void**)&pattn, g_attn);
    cudaGetSymbolAddress((void**)&pproj, g_proj);
    cudaGetSymbolAddress((void**)&penc,  g_enc);
    cudaGetSymbolAddress((void**)&pff,   g_ff);
    cudaGetSymbolAddress((void**)&ptgt,  g_tgt);
    cudaGetSymbolAddress((void**)&whi,   g_whi);
    cudaGetSymbolAddress((void**)&wlo,   g_wlo);

    float* out = (float*)d_out;

    dim3 wb(32, 8);
    dim3 gw256(256/32, 256/32);          // 256x256 weights
    // weight transpose + split (runs every launch; cheap, graph-capturable)
    wsplit_kernel<<<gw256, wb>>>(Wq_s, whi+OW_QS, wlo+OW_QS, DD, DD);
    wsplit_kernel<<<gw256, wb>>>(Wk_s, whi+OW_KS, wlo+OW_KS, DD, DD);
    wsplit_kernel<<<gw256, wb>>>(Wv_s, whi+OW_VS, wlo+OW_VS, DD, DD);
    wsplit_kernel<<<gw256, wb>>>(Wo_s, whi+OW_OS, wlo+OW_OS, DD, DD);
    wsplit_kernel<<<gw256, wb>>>(Wq_c, whi+OW_QC, wlo+OW_QC, DD, DD);
    wsplit_kernel<<<gw256, wb>>>(Wk_c, whi+OW_KC, wlo+OW_KC, DD, DD);
    wsplit_kernel<<<gw256, wb>>>(Wv_c, whi+OW_VC, wlo+OW_VC, DD, DD);
    wsplit_kernel<<<gw256, wb>>>(Wo_c, whi+OW_OC, wlo+OW_OC, DD, DD);
    wsplit_kernel<<<dim3(FFD/32, DD/32),  wb>>>(W1, whi+OW_W1, wlo+OW_W1, DD, FFD);
    wsplit_kernel<<<dim3(DD/32,  FFD/32), wb>>>(W2, whi+OW_W2, wlo+OW_W2, FFD, DD);
    wsplit_kernel<<<dim3(VVPAD/32, DD/32),wb>>>(Wf, whi+OW_WF, wlo+OW_WF, DD, VV);

    dim3 gDxD(DD/128, MROWS/128);        // (2, 32)
    dim3 gFF (FFD/128, MROWS/128);       // (16, 32)
    dim3 gV  (VVPAD/128, MROWS/128);     // (199, 32)
    dim3 gAttn(BB*HH, TT/AT_ROWS);       // (16, 32)

    embed_kernel  <<<MROWS, 256>>>(tgt_in, emb, px, ptgt);
    encmask_kernel<<<BB*SSQ, 256>>>(src, enc_in, penc);

    // ---- self attention block ----
    bf16gemm_kernel<0><<<gDxD, 256>>>(px, whi+OW_QS, wlo+OW_QS, nullptr, pq, MROWS, DD, DD);
    bf16gemm_kernel<0><<<gDxD, 256>>>(px, whi+OW_KS, wlo+OW_KS, nullptr, pk, MROWS, DD, DD);
    bf16gemm_kernel<0><<<gDxD, 256>>>(px, whi+OW_VS, wlo+OW_VS, nullptr, pv, MROWS, DD, DD);
    attn_kernel<<<gAttn, 256>>>(pq, pk, pv, pattn, ptgt, TT, TT, 1);
    bf16gemm_kernel<1><<<gDxD, 256>>>(pattn, whi+OW_OS, wlo+OW_OS, bo_s, pproj, MROWS, DD, DD);
    add_ln_kernel<<<MROWS, 256>>>(px, pproj, g1, be1, px);

    // ---- cross attention block ----
    bf16gemm_kernel<0><<<gDxD, 256>>>(px,   whi+OW_QC, wlo+OW_QC, nullptr, pq, MROWS, DD, DD);
    bf16gemm_kernel<0><<<gDxD, 256>>>(penc, whi+OW_KC, wlo+OW_KC, nullptr, pk, BB*SSQ, DD, DD);
    bf16gemm_kernel<0><<<gDxD, 256>>>(penc, whi+OW_VC, wlo+OW_VC, nullptr, pv, BB*SSQ, DD, DD);
    attn_kernel<<<gAttn, 256>>>(pq, pk, pv, pattn, ptgt, TT, SSQ, 0);
    bf16gemm_kernel<1><<<gDxD, 256>>>(pattn, whi+OW_OC, wlo+OW_OC, bo_c, pproj, MROWS, DD, DD);
    add_ln_kernel<<<MROWS, 256>>>(px, pproj, g2, be2, px);

    // ---- feed-forward ----
    bf16gemm_kernel<2><<<gFF,  256>>>(px,  whi+OW_W1, wlo+OW_W1, b1, pff,   MROWS, FFD, DD);
    bf16gemm_kernel<1><<<gDxD, 256>>>(pff, whi+OW_W2, wlo+OW_W2, b2, pproj, MROWS, DD, FFD);
    add_ln_kernel<<<MROWS, 256>>>(px, pproj, g3, be3, px);

    // ---- vocab projection straight into d_out ----
    bf16gemm_kernel<1><<<gV, 256>>>(px, whi+OW_WF, wlo+OW_WF, bf, out, MROWS, VV, DD);

    // ---- second output (tgt ids) ----
    if ((long long)out_size >= NLOGITS + MROWS) {
        write_ids_kernel<<<(MROWS + 255)/256, 256>>>(ptgt, out);
    }
}